// round 11
// baseline (speedup 1.0000x reference)
#include <cuda_runtime.h>

#define NN 50000
#define EE 300000
#define RR 4
#define FIN 11
#define HH 256
#define GG 2048
#define TT 19
#define RH 1024   // R*H
#define BN_EPS 1e-5f

// ---------------- scratch (device globals; no allocations allowed) ----------------
__device__ float g_Y[(size_t)NN * RH];            // Y = X @ w1[r] (pre-aggregation)
__device__ float g_Hcat[(size_t)NN * RH];         // [N, R*H] aggregated hidden states
__device__ float g_X0[(size_t)NN * HH];
__device__ float g_X1[(size_t)NN * HH];
__device__ float g_Wc[(size_t)(HH + RH) * HH];    // concat [sw; pad; W2cat]
__device__ float g_sums[2 * RH];                  // col sums / sumsq
__device__ float g_scale[RH];
__device__ float g_shift[RH];
__device__ float g_bias0[HH];
__device__ float g_pool[GG * HH];
__device__ float g_cnt[GG];

// int32 copies of the index tensors (robust to harness int32-vs-int64)
__device__ int g_ei[2 * EE];
__device__ int g_et[EE];
__device__ int g_batch[NN];

// CSR by (dst, relation): 4*NN sublists
__device__ int g_deg[4 * NN];
__device__ int g_off[4 * NN + 1];
__device__ int g_cur[4 * NN];
__device__ int g_adj[EE];

// ---------------- index dtype sniff + convert ----------------
__global__ void convert_idx(const int* __restrict__ ei_raw,
                            const int* __restrict__ et_raw,
                            const int* __restrict__ b_raw) {
    bool is64 = (ei_raw[1] == 0 && ei_raw[3] == 0 && ei_raw[5] == 0 && ei_raw[7] == 0);
    int i = blockIdx.x * blockDim.x + threadIdx.x;
    int stride = gridDim.x * blockDim.x;
    for (int j = i; j < 2 * EE; j += stride) g_ei[j] = is64 ? ei_raw[2 * j] : ei_raw[j];
    for (int j = i; j < EE; j += stride)     g_et[j] = is64 ? et_raw[2 * j] : et_raw[j];
    for (int j = i; j < NN; j += stride)     g_batch[j] = is64 ? b_raw[2 * j] : b_raw[j];
}

// ---------------- CSR build (once per launch) ----------------
__global__ void csr_zero() {
    int i = blockIdx.x * blockDim.x + threadIdx.x;
    if (i < 4 * NN) g_deg[i] = 0;
}

__global__ void csr_count() {
    int e = blockIdx.x * blockDim.x + threadIdx.x;
    if (e >= EE) return;
    int d = g_ei[EE + e];
    int r = g_et[e];
    atomicAdd(&g_deg[d * 4 + r], 1);
}

// single-block exclusive scan over 4*NN entries
__global__ void __launch_bounds__(1024) csr_scan() {
    const int n = 4 * NN;
    __shared__ int part[1024];
    int t = threadIdx.x;
    int chunk = (n + 1023) / 1024;
    int begin = t * chunk;
    int end = begin + chunk; if (end > n) end = n;
    int s = 0;
    for (int i = begin; i < end; i++) s += g_deg[i];
    part[t] = s;
    __syncthreads();
    for (int ofs = 1; ofs < 1024; ofs <<= 1) {
        int v = (t >= ofs) ? part[t - ofs] : 0;
        __syncthreads();
        if (t >= ofs) part[t] += v;
        __syncthreads();
    }
    int run = (t == 0) ? 0 : part[t - 1];
    for (int i = begin; i < end; i++) {
        g_off[i] = run;
        g_cur[i] = run;
        run += g_deg[i];
    }
    if (t == 1023) g_off[n] = part[1023];
}

__global__ void csr_fill() {
    int e = blockIdx.x * blockDim.x + threadIdx.x;
    if (e >= EE) return;
    int s = g_ei[e];
    int d = g_ei[EE + e];
    int r = g_et[e];
    int p = atomicAdd(&g_cur[d * 4 + r], 1);
    g_adj[p] = s;
}

// ---------------- output-space aggregation + fused BN stats ----------------
// Hcat[d, :] = Y[d, :] + sum_{s in CSR[d, q]} Y[s, :]   (q = column quarter = relation)
// Column sums/sumsq accumulated in registers -> red.v4 to g_sums.
#define AGG_ROWS 32

__global__ void __launch_bounds__(256) agg_stats() {
    int tid = threadIdx.x;
    int q = tid >> 6;                 // relation quarter owning this thread's columns
    int base = blockIdx.x * AGG_ROWS;
    const float4* Y4 = (const float4*)g_Y;
    float4* H4 = (float4*)g_Hcat;

    float4 sum = make_float4(0.f, 0.f, 0.f, 0.f);
    float4 sq  = make_float4(0.f, 0.f, 0.f, 0.f);

    for (int rr = 0; rr < AGG_ROWS; rr++) {
        int d = base + rr;
        if (d >= NN) break;
        float4 acc = Y4[(size_t)d * 256 + tid];
        int beg = g_off[d * 4 + q];
        int end = g_off[d * 4 + q + 1];
        for (int i = beg; i < end; i++) {
            int s = g_adj[i];
            float4 v = Y4[(size_t)s * 256 + tid];   // same float4 slot as owned columns
            acc.x += v.x; acc.y += v.y; acc.z += v.z; acc.w += v.w;
        }
        H4[(size_t)d * 256 + tid] = acc;
        sum.x += acc.x; sum.y += acc.y; sum.z += acc.z; sum.w += acc.w;
        sq.x += acc.x * acc.x; sq.y += acc.y * acc.y;
        sq.z += acc.z * acc.z; sq.w += acc.w * acc.w;
    }

    float* ps = &g_sums[tid * 4];
    asm volatile("red.global.add.v4.f32 [%0], {%1,%2,%3,%4};"
                 :: "l"(ps), "f"(sum.x), "f"(sum.y), "f"(sum.z), "f"(sum.w) : "memory");
    float* pq = &g_sums[RH + tid * 4];
    asm volatile("red.global.add.v4.f32 [%0], {%1,%2,%3,%4};"
                 :: "l"(pq), "f"(sq.x), "f"(sq.y), "f"(sq.z), "f"(sq.w) : "memory");
}

// concat W = [sw (fin rows); zeros (K1pad-fin rows); w2cat (RH rows)], ld 256
__global__ void concatW(const float* __restrict__ sw, const float* __restrict__ w2,
                        int fin, int k1pad) {
    int idx = blockIdx.x * blockDim.x + threadIdx.x;
    int tot = (k1pad + RH) * HH;
    if (idx >= tot) return;
    int k = idx >> 8;
    int c = idx & 255;
    float v = 0.f;
    if (k < fin)            v = sw[k * HH + c];
    else if (k >= k1pad)    v = w2[(size_t)(k - k1pad) * HH + c];
    g_Wc[idx] = v;
}

// ---------------- tf32 tensor-core GEMM: 128x128 CTA tile, 8 warps @ 32x64 ----------------
#define TBM 128
#define TBN 128
#define TBK 32

__device__ __forceinline__ unsigned f2tf(float v) {
    unsigned r;
    asm("cvt.rna.tf32.f32 %0, %1;" : "=r"(r) : "f"(v));
    return r;
}

__device__ __forceinline__ void mma8(float* c, const unsigned* a, const unsigned* b) {
    asm volatile(
        "mma.sync.aligned.m16n8k8.row.col.f32.tf32.tf32.f32 "
        "{%0,%1,%2,%3}, {%4,%5,%6,%7}, {%8,%9}, {%0,%1,%2,%3};"
        : "+f"(c[0]), "+f"(c[1]), "+f"(c[2]), "+f"(c[3])
        : "r"(a[0]), "r"(a[1]), "r"(a[2]), "r"(a[3]), "r"(b[0]), "r"(b[1]));
}

__global__ void __launch_bounds__(256)
tgemm(const float* __restrict__ A1, int K1, int K1pad, size_t bsA1,
      const float* __restrict__ A2,
      int M,
      const float* __restrict__ W, int KW, size_t bsW,
      float* __restrict__ Cwr, int ldc, int bsC,
      const float* __restrict__ bias, int relu)
{
    int bz = blockIdx.z;
    A1 += (size_t)bz * bsA1;
    W += (size_t)bz * bsW;
    int Ktot = K1pad + (A2 ? RH : 0);

    int rowBase = blockIdx.y * TBM;
    int colTile = blockIdx.x * TBN;

    __shared__ unsigned As[TBM][36];   // As[m][k], pad 36 -> conflict-free
    __shared__ unsigned Bs[TBK][136];  // Bs[k][n]

    int tid = threadIdx.x;
    int lane = tid & 31;
    int warp = tid >> 5;
    int wr = (warp >> 1) * 32;
    int wc = (warp & 1) * 64;
    int gid = lane >> 2;
    int tq = lane & 3;

    float c[2][8][4];
#pragma unroll
    for (int i = 0; i < 2; i++)
#pragma unroll
        for (int j = 0; j < 8; j++)
#pragma unroll
            for (int q = 0; q < 4; q++) c[i][j][q] = 0.f;

    int kqA = (tid & 7) * 4;       // 0..28, fixed per thread
    int rowqA = tid >> 3;          // 0..31

    for (int k0 = 0; k0 < Ktot; k0 += TBK) {
        // ---- A tile 128x32, tile-uniform region select ----
        if (k0 < K1pad) {
            if (K1 == K1pad) {
#pragma unroll
                for (int p = 0; p < 4; p++) {
                    int lr = rowqA + p * 32;
                    int row = rowBase + lr;
                    float4 v = make_float4(0.f, 0.f, 0.f, 0.f);
                    if (row < M) v = *(const float4*)(A1 + (size_t)row * K1 + k0 + kqA);
                    As[lr][kqA + 0] = f2tf(v.x);
                    As[lr][kqA + 1] = f2tf(v.y);
                    As[lr][kqA + 2] = f2tf(v.z);
                    As[lr][kqA + 3] = f2tf(v.w);
                }
            } else {
                // padded region 1 (fin==11): scalar guarded, only 1 tile
#pragma unroll
                for (int p = 0; p < 4; p++) {
                    int lr = rowqA + p * 32;
                    int row = rowBase + lr;
#pragma unroll
                    for (int j = 0; j < 4; j++) {
                        int kk = k0 + kqA + j;
                        float v = 0.f;
                        if (row < M && kk < K1) v = A1[(size_t)row * K1 + kk];
                        As[lr][kqA + j] = f2tf(v);
                    }
                }
            }
        } else {
            // region 2: Hcat with BN+ReLU; scale/shift via 2 float4 loads per tile
            int k2 = k0 - K1pad + kqA;
            float4 sc4 = *(const float4*)(g_scale + k2);
            float4 sh4 = *(const float4*)(g_shift + k2);
#pragma unroll
            for (int p = 0; p < 4; p++) {
                int lr = rowqA + p * 32;
                int row = rowBase + lr;
                float4 v = make_float4(0.f, 0.f, 0.f, 0.f);
                if (row < M) v = *(const float4*)(A2 + (size_t)row * RH + k2);
                As[lr][kqA + 0] = f2tf(fmaxf(fmaf(v.x, sc4.x, sh4.x), 0.f));
                As[lr][kqA + 1] = f2tf(fmaxf(fmaf(v.y, sc4.y, sh4.y), 0.f));
                As[lr][kqA + 2] = f2tf(fmaxf(fmaf(v.z, sc4.z, sh4.z), 0.f));
                As[lr][kqA + 3] = f2tf(fmaxf(fmaf(v.w, sc4.w, sh4.w), 0.f));
            }
        }
        // ---- W tile 32x128 (ldw = HH), vector loads ----
        {
            int nq = (tid & 31) * 4;
            int kk0 = tid >> 5;        // 0..7
#pragma unroll
            for (int p = 0; p < 4; p++) {
                int lk = kk0 + p * 8;
                int kk = k0 + lk;
                float4 v = make_float4(0.f, 0.f, 0.f, 0.f);
                if (kk < KW) v = *(const float4*)(W + (size_t)kk * HH + colTile + nq);
                Bs[lk][nq + 0] = f2tf(v.x);
                Bs[lk][nq + 1] = f2tf(v.y);
                Bs[lk][nq + 2] = f2tf(v.z);
                Bs[lk][nq + 3] = f2tf(v.w);
            }
        }
        __syncthreads();

#pragma unroll
        for (int ks = 0; ks < 4; ks++) {
            int kb = ks * 8;
            unsigned a[2][4], b[8][2];
#pragma unroll
            for (int rb = 0; rb < 2; rb++) {
                int r = wr + rb * 16 + gid;
                a[rb][0] = As[r][kb + tq];
                a[rb][1] = As[r + 8][kb + tq];
                a[rb][2] = As[r][kb + tq + 4];
                a[rb][3] = As[r + 8][kb + tq + 4];
            }
#pragma unroll
            for (int cb = 0; cb < 8; cb++) {
                int cn = wc + cb * 8 + gid;
                b[cb][0] = Bs[kb + tq][cn];
                b[cb][1] = Bs[kb + tq + 4][cn];
            }
#pragma unroll
            for (int rb = 0; rb < 2; rb++)
#pragma unroll
                for (int cb = 0; cb < 8; cb++)
                    mma8(c[rb][cb], a[rb], b[cb]);
        }
        __syncthreads();
    }

    // ---- C write ----
#pragma unroll
    for (int rb = 0; rb < 2; rb++) {
        int r0 = rowBase + wr + rb * 16 + gid;
        int r1 = r0 + 8;
#pragma unroll
        for (int cb = 0; cb < 8; cb++) {
            int lcol = colTile + wc + cb * 8 + tq * 2;
#pragma unroll
            for (int j = 0; j < 2; j++) {
                int col = lcol + j;
                float bsum = bias ? bias[col] : 0.f;
                if (r0 < M) {
                    float v = c[rb][cb][j] + bsum;
                    if (relu) v = fmaxf(v, 0.f);
                    Cwr[(size_t)r0 * ldc + bz * bsC + col] = v;
                }
                if (r1 < M) {
                    float v = c[rb][cb][2 + j] + bsum;
                    if (relu) v = fmaxf(v, 0.f);
                    Cwr[(size_t)r1 * ldc + bz * bsC + col] = v;
                }
            }
        }
    }
}

// ---------------- BatchNorm param finalize ----------------
__global__ void zero_stats() {
    int i = blockIdx.x * blockDim.x + threadIdx.x;
    if (i < 2 * RH) g_sums[i] = 0.f;
}

__global__ void bn_finalize(const float* __restrict__ g, const float* __restrict__ bt) {
    int c = blockIdx.x * blockDim.x + threadIdx.x;
    if (c < RH) {
        float mu  = g_sums[c] * (1.0f / NN);
        float var = g_sums[RH + c] * (1.0f / NN) - mu * mu;
        float sc  = g[c] * rsqrtf(var + BN_EPS);
        g_scale[c] = sc;
        g_shift[c] = bt[c] - mu * sc;
    }
}

// bias0 = sb + sum_r b2_r   (b1 cancels inside BN, so it's dropped)
__global__ void bias0_kernel(const float* __restrict__ sb, const float* __restrict__ b2) {
    int c = threadIdx.x;
    g_bias0[c] = sb[c] + b2[c] + b2[HH + c] + b2[2 * HH + c] + b2[3 * HH + c];
}

// ---------------- pooling + final linear ----------------
__global__ void pool_zero() {
    int i = blockIdx.x * blockDim.x + threadIdx.x;
    if (i < GG * HH) g_pool[i] = 0.f;
    if (i < GG) g_cnt[i] = 0.f;
}

__global__ void pool_scatter_v4(const float* __restrict__ X) {
    int gid = blockIdx.x * blockDim.x + threadIdx.x;
    int n = gid >> 6;
    int q = gid & 63;
    if (n >= NN) return;
    int b = g_batch[n];
    float4 v = __ldg((const float4*)(X + (size_t)n * HH) + q);
    float* p = &g_pool[b * HH + q * 4];
    asm volatile("red.global.add.v4.f32 [%0], {%1,%2,%3,%4};"
                 :: "l"(p), "f"(v.x), "f"(v.y), "f"(v.z), "f"(v.w) : "memory");
    if (q == 0) atomicAdd(&g_cnt[b], 1.f);
}

__global__ void final_linear(const float* __restrict__ lw, const float* __restrict__ lb,
                             float* __restrict__ out) {
    __shared__ float sh[HH];
    int g = blockIdx.x;
    float inv = 1.0f / fmaxf(g_cnt[g], 1.f);
    sh[threadIdx.x] = g_pool[g * HH + threadIdx.x] * inv;
    __syncthreads();
    if (threadIdx.x < TT) {
        int t = threadIdx.x;
        float acc = lb[t];
#pragma unroll 8
        for (int c = 0; c < HH; c++) acc += sh[c] * lw[c * TT + t];
        out[g * TT + t] = acc;
    }
}

// ---------------- orchestration ----------------
static void run_layer(const float* Xin, int fin,
                      const float* sw, const float* sb, const float* w1,
                      const float* gamma, const float* beta,
                      const float* w2, const float* b2,
                      float* pY, float* pHcat, float* pWc, float* pBias0,
                      float* Xout)
{
    int k1pad = (fin == FIN) ? 32 : HH;   // multiple of TBK
    int mtiles = (NN + TBM - 1) / TBM;

    // 1. Y[:, r*H:(r+1)*H] = X @ w1[r]  (directly from X: no copy, no scatter on X)
    zero_stats<<<2, 1024>>>();
    tgemm<<<dim3(HH / TBN, mtiles, RR), 256>>>(
        Xin, fin, (fin == FIN) ? 32 : fin, /*bsA1=*/0,
        nullptr,
        NN,
        w1, fin, (size_t)fin * HH,
        pY, RH, HH, nullptr, 0);

    // 2. Hcat[d] = Y[d] + sum_{edges to d} Y[src]  (CSR gather, fused BN stats)
    agg_stats<<<(NN + AGG_ROWS - 1) / AGG_ROWS, 256>>>();

    // 3. BN scale/shift + fused biases + concat weights [sw; pad; W2cat]
    bn_finalize<<<4, 256>>>(gamma, beta);
    bias0_kernel<<<1, 256>>>(sb, b2);
    concatW<<<((k1pad + RH) * HH + 255) / 256, 256>>>(sw, w2, fin, k1pad);

    // 4. Xout = relu( [Xin|pad | bn_relu(Hcat)] @ Wc + bias0 )
    tgemm<<<dim3(HH / TBN, mtiles, 1), 256>>>(
        Xin, fin, k1pad, 0,
        pHcat,
        NN,
        pWc, k1pad + RH, 0,
        Xout, HH, 0, pBias0, /*relu=*/1);
}

extern "C" void kernel_launch(void* const* d_in, const int* in_sizes, int n_in,
                              void* d_out, int out_size)
{
    const float* x     = (const float*)d_in[0];
    const int*   ei    = (const int*)d_in[1];   // int32 OR int64 raw words (sniffed)
    const int*   et    = (const int*)d_in[2];
    const int*   batch = (const int*)d_in[3];
    const float* lin_w = (const float*)d_in[28];
    const float* lin_b = (const float*)d_in[29];

    float *pY, *pHcat, *pX0, *pX1, *pWc, *pBias0;
    cudaGetSymbolAddress((void**)&pY, g_Y);
    cudaGetSymbolAddress((void**)&pHcat, g_Hcat);
    cudaGetSymbolAddress((void**)&pX0, g_X0);
    cudaGetSymbolAddress((void**)&pX1, g_X1);
    cudaGetSymbolAddress((void**)&pWc, g_Wc);
    cudaGetSymbolAddress((void**)&pBias0, g_bias0);

    // normalize indices to int32 scratch (handles int32 or int64 inputs)
    convert_idx<<<1024, 256>>>(ei, et, batch);

    // build per-(dst, relation) CSR once
    csr_zero<<<(4 * NN + 255) / 256, 256>>>();
    csr_count<<<(EE + 255) / 256, 256>>>();
    csr_scan<<<1, 1024>>>();
    csr_fill<<<(EE + 255) / 256, 256>>>();

    // layer params: base = 4 + 8*l : sw, sb, w1, b1(unused), g, bt, w2, b2
    const float* Xcur = x;
    float* outs[3] = {pX0, pX1, pX0};
    int fins[3] = {FIN, HH, HH};
    for (int l = 0; l < 3; l++) {
        int base = 4 + 8 * l;
        run_layer(Xcur, fins[l],
                  (const float*)d_in[base + 0], (const float*)d_in[base + 1],
                  (const float*)d_in[base + 2],
                  (const float*)d_in[base + 4], (const float*)d_in[base + 5],
                  (const float*)d_in[base + 6], (const float*)d_in[base + 7],
                  pY, pHcat, pWc, pBias0, outs[l]);
        Xcur = outs[l];
    }

    // global mean pool + final linear
    pool_zero<<<(GG * HH + 255) / 256, 256>>>();
    pool_scatter_v4<<<(NN * 64 + 255) / 256, 256>>>(Xcur);
    final_linear<<<GG, HH>>>(lin_w, lin_b, (float*)d_out);
}

// round 12
// speedup vs baseline: 1.1659x; 1.1659x over previous
#include <cuda_runtime.h>

#define NN 50000
#define EE 300000
#define RR 4
#define FIN 11
#define HH 256
#define GG 2048
#define TT 19
#define RH 1024   // R*H
#define BN_EPS 1e-5f

#define CSR_N (4 * NN)
#define CSR_BLK 256
#define CSR_NBLK ((CSR_N + CSR_BLK - 1) / CSR_BLK)   // 782

// ---------------- scratch (device globals; no allocations allowed) ----------------
__device__ float g_Y[(size_t)NN * RH];            // Y = X @ w1[r] (pre-aggregation)
__device__ float g_Hcat[(size_t)NN * RH];         // [N, R*H] aggregated hidden states
__device__ float g_X0[(size_t)NN * HH];
__device__ float g_X1[(size_t)NN * HH];
__device__ float g_Wc[(size_t)(HH + RH) * HH];    // concat [sw; pad; W2cat]
__device__ float g_sums[2 * RH];                  // col sums / sumsq
__device__ float g_scale[RH];
__device__ float g_shift[RH];
__device__ float g_bias0[HH];
__device__ float g_pool[GG * HH];
__device__ float g_cnt[GG];

// int32 copies of the index tensors (robust to harness int32-vs-int64)
__device__ int g_ei[2 * EE];
__device__ int g_et[EE];
__device__ int g_batch[NN];

// CSR by (dst, relation): 4*NN sublists
__device__ int g_deg[CSR_N];
__device__ int g_off[CSR_N + 1];
__device__ int g_cur[CSR_N];
__device__ int g_adj[EE];
__device__ int g_bsum[CSR_NBLK];
__device__ int g_boff[CSR_NBLK];

// ---------------- index dtype sniff + convert ----------------
__global__ void convert_idx(const int* __restrict__ ei_raw,
                            const int* __restrict__ et_raw,
                            const int* __restrict__ b_raw) {
    bool is64 = (ei_raw[1] == 0 && ei_raw[3] == 0 && ei_raw[5] == 0 && ei_raw[7] == 0);
    int i = blockIdx.x * blockDim.x + threadIdx.x;
    int stride = gridDim.x * blockDim.x;
    for (int j = i; j < 2 * EE; j += stride) g_ei[j] = is64 ? ei_raw[2 * j] : ei_raw[j];
    for (int j = i; j < EE; j += stride)     g_et[j] = is64 ? et_raw[2 * j] : et_raw[j];
    for (int j = i; j < NN; j += stride)     g_batch[j] = is64 ? b_raw[2 * j] : b_raw[j];
}

// ---------------- CSR build (once per launch) ----------------
__global__ void csr_zero() {
    int i = blockIdx.x * blockDim.x + threadIdx.x;
    if (i < CSR_N) g_deg[i] = 0;
}

__global__ void csr_count() {
    int e = blockIdx.x * blockDim.x + threadIdx.x;
    if (e >= EE) return;
    int d = g_ei[EE + e];
    int r = g_et[e];
    atomicAdd(&g_deg[d * 4 + r], 1);
}

// Phase A: per-block sums of 256 degrees
__global__ void __launch_bounds__(CSR_BLK) csr_block_sum() {
    __shared__ int sh[CSR_BLK];
    int i = blockIdx.x * CSR_BLK + threadIdx.x;
    sh[threadIdx.x] = (i < CSR_N) ? g_deg[i] : 0;
    __syncthreads();
    for (int s = CSR_BLK / 2; s > 0; s >>= 1) {
        if (threadIdx.x < s) sh[threadIdx.x] += sh[threadIdx.x + s];
        __syncthreads();
    }
    if (threadIdx.x == 0) g_bsum[blockIdx.x] = sh[0];
}

// Phase B: single-block scan of the 782 block sums (all in shared)
__global__ void __launch_bounds__(1024) csr_scan_bsums() {
    __shared__ int sh[1024];
    int t = threadIdx.x;
    sh[t] = (t < CSR_NBLK) ? g_bsum[t] : 0;
    __syncthreads();
    for (int ofs = 1; ofs < 1024; ofs <<= 1) {
        int v = (t >= ofs) ? sh[t - ofs] : 0;
        __syncthreads();
        sh[t] += v;
        __syncthreads();
    }
    if (t < CSR_NBLK) g_boff[t] = (t == 0) ? 0 : sh[t - 1];
    if (t == 0) g_off[CSR_N] = sh[1023];   // total == EE
}

// Phase C: in-block exclusive scan + block offset -> g_off, g_cur
__global__ void __launch_bounds__(CSR_BLK) csr_offsets() {
    __shared__ int sh[CSR_BLK];
    int i = blockIdx.x * CSR_BLK + threadIdx.x;
    int t = threadIdx.x;
    int d = (i < CSR_N) ? g_deg[i] : 0;
    sh[t] = d;
    __syncthreads();
    for (int ofs = 1; ofs < CSR_BLK; ofs <<= 1) {
        int v = (t >= ofs) ? sh[t - ofs] : 0;
        __syncthreads();
        sh[t] += v;
        __syncthreads();
    }
    if (i < CSR_N) {
        int excl = sh[t] - d + g_boff[blockIdx.x];
        g_off[i] = excl;
        g_cur[i] = excl;
    }
}

__global__ void csr_fill() {
    int e = blockIdx.x * blockDim.x + threadIdx.x;
    if (e >= EE) return;
    int s = g_ei[e];
    int d = g_ei[EE + e];
    int r = g_et[e];
    int p = atomicAdd(&g_cur[d * 4 + r], 1);
    g_adj[p] = s;
}

// ---------------- output-space aggregation + fused BN stats ----------------
// Hcat[d, :] = Y[d, :] + sum_{s in CSR[d, q]} Y[s, :]   (q = column quarter = relation)
#define AGG_ROWS 32

__global__ void __launch_bounds__(256) agg_stats() {
    int tid = threadIdx.x;
    int q = tid >> 6;                 // relation quarter owning this thread's columns
    int base = blockIdx.x * AGG_ROWS;
    const float4* Y4 = (const float4*)g_Y;
    float4* H4 = (float4*)g_Hcat;

    float4 sum = make_float4(0.f, 0.f, 0.f, 0.f);
    float4 sq  = make_float4(0.f, 0.f, 0.f, 0.f);

    for (int rr = 0; rr < AGG_ROWS; rr++) {
        int d = base + rr;
        if (d >= NN) break;
        float4 acc = Y4[(size_t)d * 256 + tid];
        int beg = g_off[d * 4 + q];
        int end = g_off[d * 4 + q + 1];
        for (int i = beg; i < end; i++) {
            int s = g_adj[i];
            float4 v = Y4[(size_t)s * 256 + tid];
            acc.x += v.x; acc.y += v.y; acc.z += v.z; acc.w += v.w;
        }
        H4[(size_t)d * 256 + tid] = acc;
        sum.x += acc.x; sum.y += acc.y; sum.z += acc.z; sum.w += acc.w;
        sq.x += acc.x * acc.x; sq.y += acc.y * acc.y;
        sq.z += acc.z * acc.z; sq.w += acc.w * acc.w;
    }

    float* ps = &g_sums[tid * 4];
    asm volatile("red.global.add.v4.f32 [%0], {%1,%2,%3,%4};"
                 :: "l"(ps), "f"(sum.x), "f"(sum.y), "f"(sum.z), "f"(sum.w) : "memory");
    float* pq = &g_sums[RH + tid * 4];
    asm volatile("red.global.add.v4.f32 [%0], {%1,%2,%3,%4};"
                 :: "l"(pq), "f"(sq.x), "f"(sq.y), "f"(sq.z), "f"(sq.w) : "memory");
}

// concat W = [sw (fin rows); zeros (K1pad-fin rows); w2cat (RH rows)], ld 256
__global__ void concatW(const float* __restrict__ sw, const float* __restrict__ w2,
                        int fin, int k1pad) {
    int idx = blockIdx.x * blockDim.x + threadIdx.x;
    int tot = (k1pad + RH) * HH;
    if (idx >= tot) return;
    int k = idx >> 8;
    int c = idx & 255;
    float v = 0.f;
    if (k < fin)            v = sw[k * HH + c];
    else if (k >= k1pad)    v = w2[(size_t)(k - k1pad) * HH + c];
    g_Wc[idx] = v;
}

// ---------------- tf32 tensor-core GEMM: 128x128 CTA tile, 8 warps @ 32x64 ----------------
#define TBM 128
#define TBN 128
#define TBK 32

__device__ __forceinline__ unsigned f2tf(float v) {
    unsigned r;
    asm("cvt.rna.tf32.f32 %0, %1;" : "=r"(r) : "f"(v));
    return r;
}

__device__ __forceinline__ void mma8(float* c, const unsigned* a, const unsigned* b) {
    asm volatile(
        "mma.sync.aligned.m16n8k8.row.col.f32.tf32.tf32.f32 "
        "{%0,%1,%2,%3}, {%4,%5,%6,%7}, {%8,%9}, {%0,%1,%2,%3};"
        : "+f"(c[0]), "+f"(c[1]), "+f"(c[2]), "+f"(c[3])
        : "r"(a[0]), "r"(a[1]), "r"(a[2]), "r"(a[3]), "r"(b[0]), "r"(b[1]));
}

__global__ void __launch_bounds__(256)
tgemm(const float* __restrict__ A1, int K1, int K1pad, size_t bsA1,
      const float* __restrict__ A2,
      int M,
      const float* __restrict__ W, int KW, size_t bsW,
      float* __restrict__ Cwr, int ldc, int bsC,
      const float* __restrict__ bias, int relu)
{
    int bz = blockIdx.z;
    A1 += (size_t)bz * bsA1;
    W += (size_t)bz * bsW;
    int Ktot = K1pad + (A2 ? RH : 0);

    int rowBase = blockIdx.y * TBM;
    int colTile = blockIdx.x * TBN;

    __shared__ unsigned As[TBM][36];   // As[m][k], pad 36 -> conflict-free
    __shared__ unsigned Bs[TBK][136];  // Bs[k][n]

    int tid = threadIdx.x;
    int lane = tid & 31;
    int warp = tid >> 5;
    int wr = (warp >> 1) * 32;
    int wc = (warp & 1) * 64;
    int gid = lane >> 2;
    int tq = lane & 3;

    float c[2][8][4];
#pragma unroll
    for (int i = 0; i < 2; i++)
#pragma unroll
        for (int j = 0; j < 8; j++)
#pragma unroll
            for (int q = 0; q < 4; q++) c[i][j][q] = 0.f;

    int kqA = (tid & 7) * 4;       // 0..28, fixed per thread
    int rowqA = tid >> 3;          // 0..31

    for (int k0 = 0; k0 < Ktot; k0 += TBK) {
        // ---- A tile 128x32, tile-uniform region select ----
        if (k0 < K1pad) {
            if (K1 == K1pad) {
#pragma unroll
                for (int p = 0; p < 4; p++) {
                    int lr = rowqA + p * 32;
                    int row = rowBase + lr;
                    float4 v = make_float4(0.f, 0.f, 0.f, 0.f);
                    if (row < M) v = *(const float4*)(A1 + (size_t)row * K1 + k0 + kqA);
                    As[lr][kqA + 0] = f2tf(v.x);
                    As[lr][kqA + 1] = f2tf(v.y);
                    As[lr][kqA + 2] = f2tf(v.z);
                    As[lr][kqA + 3] = f2tf(v.w);
                }
            } else {
                // padded region 1 (fin==11): scalar guarded, only 1 tile
#pragma unroll
                for (int p = 0; p < 4; p++) {
                    int lr = rowqA + p * 32;
                    int row = rowBase + lr;
#pragma unroll
                    for (int j = 0; j < 4; j++) {
                        int kk = k0 + kqA + j;
                        float v = 0.f;
                        if (row < M && kk < K1) v = A1[(size_t)row * K1 + kk];
                        As[lr][kqA + j] = f2tf(v);
                    }
                }
            }
        } else {
            // region 2: Hcat with BN+ReLU; scale/shift via 2 float4 loads per tile
            int k2 = k0 - K1pad + kqA;
            float4 sc4 = *(const float4*)(g_scale + k2);
            float4 sh4 = *(const float4*)(g_shift + k2);
#pragma unroll
            for (int p = 0; p < 4; p++) {
                int lr = rowqA + p * 32;
                int row = rowBase + lr;
                float4 v = make_float4(0.f, 0.f, 0.f, 0.f);
                if (row < M) v = *(const float4*)(A2 + (size_t)row * RH + k2);
                As[lr][kqA + 0] = f2tf(fmaxf(fmaf(v.x, sc4.x, sh4.x), 0.f));
                As[lr][kqA + 1] = f2tf(fmaxf(fmaf(v.y, sc4.y, sh4.y), 0.f));
                As[lr][kqA + 2] = f2tf(fmaxf(fmaf(v.z, sc4.z, sh4.z), 0.f));
                As[lr][kqA + 3] = f2tf(fmaxf(fmaf(v.w, sc4.w, sh4.w), 0.f));
            }
        }
        // ---- W tile 32x128 (ldw = HH), vector loads ----
        {
            int nq = (tid & 31) * 4;
            int kk0 = tid >> 5;        // 0..7
#pragma unroll
            for (int p = 0; p < 4; p++) {
                int lk = kk0 + p * 8;
                int kk = k0 + lk;
                float4 v = make_float4(0.f, 0.f, 0.f, 0.f);
                if (kk < KW) v = *(const float4*)(W + (size_t)kk * HH + colTile + nq);
                Bs[lk][nq + 0] = f2tf(v.x);
                Bs[lk][nq + 1] = f2tf(v.y);
                Bs[lk][nq + 2] = f2tf(v.z);
                Bs[lk][nq + 3] = f2tf(v.w);
            }
        }
        __syncthreads();

#pragma unroll
        for (int ks = 0; ks < 4; ks++) {
            int kb = ks * 8;
            unsigned a[2][4], b[8][2];
#pragma unroll
            for (int rb = 0; rb < 2; rb++) {
                int r = wr + rb * 16 + gid;
                a[rb][0] = As[r][kb + tq];
                a[rb][1] = As[r + 8][kb + tq];
                a[rb][2] = As[r][kb + tq + 4];
                a[rb][3] = As[r + 8][kb + tq + 4];
            }
#pragma unroll
            for (int cb = 0; cb < 8; cb++) {
                int cn = wc + cb * 8 + gid;
                b[cb][0] = Bs[kb + tq][cn];
                b[cb][1] = Bs[kb + tq + 4][cn];
            }
#pragma unroll
            for (int rb = 0; rb < 2; rb++)
#pragma unroll
                for (int cb = 0; cb < 8; cb++)
                    mma8(c[rb][cb], a[rb], b[cb]);
        }
        __syncthreads();
    }

    // ---- C write ----
#pragma unroll
    for (int rb = 0; rb < 2; rb++) {
        int r0 = rowBase + wr + rb * 16 + gid;
        int r1 = r0 + 8;
#pragma unroll
        for (int cb = 0; cb < 8; cb++) {
            int lcol = colTile + wc + cb * 8 + tq * 2;
#pragma unroll
            for (int j = 0; j < 2; j++) {
                int col = lcol + j;
                float bsum = bias ? bias[col] : 0.f;
                if (r0 < M) {
                    float v = c[rb][cb][j] + bsum;
                    if (relu) v = fmaxf(v, 0.f);
                    Cwr[(size_t)r0 * ldc + bz * bsC + col] = v;
                }
                if (r1 < M) {
                    float v = c[rb][cb][2 + j] + bsum;
                    if (relu) v = fmaxf(v, 0.f);
                    Cwr[(size_t)r1 * ldc + bz * bsC + col] = v;
                }
            }
        }
    }
}

// ---------------- BatchNorm param finalize ----------------
__global__ void zero_stats() {
    int i = blockIdx.x * blockDim.x + threadIdx.x;
    if (i < 2 * RH) g_sums[i] = 0.f;
}

__global__ void bn_finalize(const float* __restrict__ g, const float* __restrict__ bt) {
    int c = blockIdx.x * blockDim.x + threadIdx.x;
    if (c < RH) {
        float mu  = g_sums[c] * (1.0f / NN);
        float var = g_sums[RH + c] * (1.0f / NN) - mu * mu;
        float sc  = g[c] * rsqrtf(var + BN_EPS);
        g_scale[c] = sc;
        g_shift[c] = bt[c] - mu * sc;
    }
}

// bias0 = sb + sum_r b2_r   (b1 cancels inside BN, so it's dropped)
__global__ void bias0_kernel(const float* __restrict__ sb, const float* __restrict__ b2) {
    int c = threadIdx.x;
    g_bias0[c] = sb[c] + b2[c] + b2[HH + c] + b2[2 * HH + c] + b2[3 * HH + c];
}

// ---------------- pooling + final linear ----------------
__global__ void pool_zero() {
    int i = blockIdx.x * blockDim.x + threadIdx.x;
    if (i < GG * HH) g_pool[i] = 0.f;
    if (i < GG) g_cnt[i] = 0.f;
}

__global__ void pool_scatter_v4(const float* __restrict__ X) {
    int gid = blockIdx.x * blockDim.x + threadIdx.x;
    int n = gid >> 6;
    int q = gid & 63;
    if (n >= NN) return;
    int b = g_batch[n];
    float4 v = __ldg((const float4*)(X + (size_t)n * HH) + q);
    float* p = &g_pool[b * HH + q * 4];
    asm volatile("red.global.add.v4.f32 [%0], {%1,%2,%3,%4};"
                 :: "l"(p), "f"(v.x), "f"(v.y), "f"(v.z), "f"(v.w) : "memory");
    if (q == 0) atomicAdd(&g_cnt[b], 1.f);
}

__global__ void final_linear(const float* __restrict__ lw, const float* __restrict__ lb,
                             float* __restrict__ out) {
    __shared__ float sh[HH];
    int g = blockIdx.x;
    float inv = 1.0f / fmaxf(g_cnt[g], 1.f);
    sh[threadIdx.x] = g_pool[g * HH + threadIdx.x] * inv;
    __syncthreads();
    if (threadIdx.x < TT) {
        int t = threadIdx.x;
        float acc = lb[t];
#pragma unroll 8
        for (int c = 0; c < HH; c++) acc += sh[c] * lw[c * TT + t];
        out[g * TT + t] = acc;
    }
}

// ---------------- orchestration ----------------
static void run_layer(const float* Xin, int fin,
                      const float* sw, const float* sb, const float* w1,
                      const float* gamma, const float* beta,
                      const float* w2, const float* b2,
                      float* pY, float* pHcat, float* pWc, float* pBias0,
                      float* Xout)
{
    int k1pad = (fin == FIN) ? 32 : HH;   // multiple of TBK
    int mtiles = (NN + TBM - 1) / TBM;

    // 1. Y[:, r*H:(r+1)*H] = X @ w1[r]  (directly from X: no copy, no scatter on X)
    zero_stats<<<2, 1024>>>();
    tgemm<<<dim3(HH / TBN, mtiles, RR), 256>>>(
        Xin, fin, (fin == FIN) ? 32 : fin, /*bsA1=*/0,
        nullptr,
        NN,
        w1, fin, (size_t)fin * HH,
        pY, RH, HH, nullptr, 0);

    // 2. Hcat[d] = Y[d] + sum_{edges to d} Y[src]  (CSR gather, fused BN stats)
    agg_stats<<<(NN + AGG_ROWS - 1) / AGG_ROWS, 256>>>();

    // 3. BN scale/shift + fused biases + concat weights [sw; pad; W2cat]
    bn_finalize<<<4, 256>>>(gamma, beta);
    bias0_kernel<<<1, 256>>>(sb, b2);
    concatW<<<((k1pad + RH) * HH + 255) / 256, 256>>>(sw, w2, fin, k1pad);

    // 4. Xout = relu( [Xin|pad | bn_relu(Hcat)] @ Wc + bias0 )
    tgemm<<<dim3(HH / TBN, mtiles, 1), 256>>>(
        Xin, fin, k1pad, 0,
        pHcat,
        NN,
        pWc, k1pad + RH, 0,
        Xout, HH, 0, pBias0, /*relu=*/1);
}

extern "C" void kernel_launch(void* const* d_in, const int* in_sizes, int n_in,
                              void* d_out, int out_size)
{
    const float* x     = (const float*)d_in[0];
    const int*   ei    = (const int*)d_in[1];   // int32 OR int64 raw words (sniffed)
    const int*   et    = (const int*)d_in[2];
    const int*   batch = (const int*)d_in[3];
    const float* lin_w = (const float*)d_in[28];
    const float* lin_b = (const float*)d_in[29];

    float *pY, *pHcat, *pX0, *pX1, *pWc, *pBias0;
    cudaGetSymbolAddress((void**)&pY, g_Y);
    cudaGetSymbolAddress((void**)&pHcat, g_Hcat);
    cudaGetSymbolAddress((void**)&pX0, g_X0);
    cudaGetSymbolAddress((void**)&pX1, g_X1);
    cudaGetSymbolAddress((void**)&pWc, g_Wc);
    cudaGetSymbolAddress((void**)&pBias0, g_bias0);

    // normalize indices to int32 scratch (handles int32 or int64 inputs)
    convert_idx<<<1024, 256>>>(ei, et, batch);

    // build per-(dst, relation) CSR once — hierarchical 3-phase scan
    csr_zero<<<(CSR_N + 255) / 256, 256>>>();
    csr_count<<<(EE + 255) / 256, 256>>>();
    csr_block_sum<<<CSR_NBLK, CSR_BLK>>>();
    csr_scan_bsums<<<1, 1024>>>();
    csr_offsets<<<CSR_NBLK, CSR_BLK>>>();
    csr_fill<<<(EE + 255) / 256, 256>>>();

    // layer params: base = 4 + 8*l : sw, sb, w1, b1(unused), g, bt, w2, b2
    const float* Xcur = x;
    float* outs[3] = {pX0, pX1, pX0};
    int fins[3] = {FIN, HH, HH};
    for (int l = 0; l < 3; l++) {
        int base = 4 + 8 * l;
        run_layer(Xcur, fins[l],
                  (const float*)d_in[base + 0], (const float*)d_in[base + 1],
                  (const float*)d_in[base + 2],
                  (const float*)d_in[base + 4], (const float*)d_in[base + 5],
                  (const float*)d_in[base + 6], (const float*)d_in[base + 7],
                  pY, pHcat, pWc, pBias0, outs[l]);
        Xcur = outs[l];
    }

    // global mean pool + final linear
    pool_zero<<<(GG * HH + 255) / 256, 256>>>();
    pool_scatter_v4<<<(NN * 64 + 255) / 256, 256>>>(Xcur);
    final_linear<<<GG, HH>>>(lin_w, lin_b, (float*)d_out);
}